// round 6
// baseline (speedup 1.0000x reference)
#include <cuda_runtime.h>
#include <cuda_bf16.h>
#include <mma.h>
#include <cstdint>

using namespace nvcuda;

// ---------------- problem constants ----------------
#define BB   32
#define HH   56
#define WW   56
#define CC   192
#define NHD  6
#define WSZ  7
#define SSH  3
#define NN   49          // WSZ*WSZ
#define HD   32          // CC/NHD
#define HID  768         // 4*CC
#define NWIN 64          // (H/WS)*(W/WS)
#define BW   2048        // BB*NWIN
#define MTOK 100352      // BW*NN  (= BB*HH*WW)

// ---------------- scratch (static device globals; aliased live ranges) ------
// g_buf1: xw (step1-2) -> att (step3-4) -> h2 (step5-6)
// g_buf2: qkv (step2-3, MTOK*576 floats) -> hid (step6-7, MTOK*768)
// g_x1  : live step4..end
__device__ float g_buf1[(size_t)MTOK * CC];
__device__ float g_buf2[(size_t)MTOK * HID];
__device__ float g_x1 [(size_t)MTOK * CC];
__device__ int   g_map[MTOK];

// ---------------- helpers ----------------------------------------------------
__device__ __forceinline__ uint32_t smem_u32(const void* p) {
    return (uint32_t)__cvta_generic_to_shared(p);
}
__device__ __forceinline__ void cp_async16(void* dst_smem, const void* src_g) {
    asm volatile("cp.async.cg.shared.global [%0], [%1], 16;\n"
                 :: "r"(smem_u32(dst_smem)), "l"(src_g));
}
__device__ __forceinline__ void cp_commit() {
    asm volatile("cp.async.commit_group;\n");
}
__device__ __forceinline__ void cp_wait0() {
    asm volatile("cp.async.wait_group 0;\n");
}

// ---------------- K1: LN + shift(-3,-3) + window partition ------------------
__global__ void __launch_bounds__(256)
ln_shift_part_kernel(const float* __restrict__ x,
                     const float* __restrict__ nw,
                     const float* __restrict__ nb,
                     float* __restrict__ xw,
                     int* __restrict__ map)
{
    int t    = blockIdx.x * 8 + (threadIdx.x >> 5);
    int lane = threadIdx.x & 31;

    int bw = t / NN, n = t - bw * NN;
    int b  = bw >> 6, wi = bw & 63;
    int wh = wi >> 3, wwp = wi & 7;
    int r  = n / WSZ, s = n - r * WSZ;
    int gh = wh * WSZ + r + SSH;  if (gh >= HH) gh -= HH;
    int gw = wwp * WSZ + s + SSH; if (gw >= WW) gw -= WW;
    int src = b * (HH * WW) + gh * WW + gw;

    const float* px = x + (size_t)src * CC;
    float v[6];
    float sum = 0.f, sq = 0.f;
#pragma unroll
    for (int i = 0; i < 6; i++) {
        v[i] = px[lane + i * 32];
        sum += v[i];
        sq  += v[i] * v[i];
    }
#pragma unroll
    for (int o = 16; o; o >>= 1) {
        sum += __shfl_xor_sync(0xffffffffu, sum, o);
        sq  += __shfl_xor_sync(0xffffffffu, sq,  o);
    }
    float mu   = sum * (1.f / CC);
    float var  = sq * (1.f / CC) - mu * mu;
    float rstd = rsqrtf(var + 1e-5f);

    float* po = xw + (size_t)t * CC;
#pragma unroll
    for (int i = 0; i < 6; i++) {
        int c = lane + i * 32;
        po[c] = (v[i] - mu) * rstd * nw[c] + nb[c];
    }
    if (lane == 0) map[t] = src;
}

// ---------------- K5: plain LN over x1 --------------------------------------
__global__ void __launch_bounds__(256)
ln_plain_kernel(const float* __restrict__ x,
                const float* __restrict__ nw,
                const float* __restrict__ nb,
                float* __restrict__ y)
{
    int t    = blockIdx.x * 8 + (threadIdx.x >> 5);
    int lane = threadIdx.x & 31;
    const float* px = x + (size_t)t * CC;
    float v[6];
    float sum = 0.f, sq = 0.f;
#pragma unroll
    for (int i = 0; i < 6; i++) {
        v[i] = px[lane + i * 32];
        sum += v[i];
        sq  += v[i] * v[i];
    }
#pragma unroll
    for (int o = 16; o; o >>= 1) {
        sum += __shfl_xor_sync(0xffffffffu, sum, o);
        sq  += __shfl_xor_sync(0xffffffffu, sq,  o);
    }
    float mu   = sum * (1.f / CC);
    float var  = sq * (1.f / CC) - mu * mu;
    float rstd = rsqrtf(var + 1e-5f);
    float* po = y + (size_t)t * CC;
#pragma unroll
    for (int i = 0; i < 6; i++) {
        int c = lane + i * 32;
        po[c] = (v[i] - mu) * rstd * nw[c] + nb[c];
    }
}

// ---------------- TF32 wmma GEMM:  Y[M,N] = X[M,K] @ W[N,K]^T + bias --------
// block tile 128x64, 8 warps (4x2), cp.async double-buffered mainloop.
#define GBM 128
#define GBN 64
#define GBK 16
#define KPAD 20          // floats per smem row (80 B, 16B-aligned)
#define CPAD 68

#define AS_FLOATS (2 * GBM * KPAD)           // 5120
#define BS_FLOATS (2 * GBN * KPAD)           // 2560
#define SMEM_FLOATS (GBM * CPAD)             // 8704 (>= 7680 pipeline floats)

__device__ __forceinline__ float gelu_exact(float v) {
    return 0.5f * v * (1.0f + erff(v * 0.70710678118654752f));
}

// EPI: 0=bias, 1=bias+gelu, 2=proj scatter (+x residual via map), 3=fc2 (+x1 residual)
template<int EPI>
__global__ void __launch_bounds__(256)
gemm_tf32(const float* __restrict__ X,
          const float* __restrict__ Wt,
          const float* __restrict__ bias,
          float* __restrict__ dst,
          int K, int Ntot,
          const float* __restrict__ res,
          const int* __restrict__ map)
{
    __shared__ __align__(16) float smem[SMEM_FLOATS];   // 34816 B, unioned
    float (*As)[GBM][KPAD] = (float(*)[GBM][KPAD])smem;             // As[2][GBM][KPAD]
    float (*Bs)[GBN][KPAD] = (float(*)[GBN][KPAD])(smem + AS_FLOATS); // Bs[2][GBN][KPAD]
    float (*Cs)[CPAD]      = (float(*)[CPAD])smem;

    int tid  = threadIdx.x;
    int warp = tid >> 5;
    int wm = warp & 3;       // 0..3  (M sub-tile)
    int wn = warp >> 2;      // 0..1  (N sub-tile)
    int bm = blockIdx.x * GBM;
    int bn = blockIdx.y * GBN;

    // per-thread load coordinates
    int ar0 = tid >> 2;               // A row for first float4 (0..63)
    int ac  = (tid & 3) << 2;         // A col (0,4,8,12)
    int br  = tid >> 2;               // B row (0..63)

    wmma::fragment<wmma::accumulator, 16, 16, 8, float> acc[2][2];
#pragma unroll
    for (int i = 0; i < 2; i++)
#pragma unroll
        for (int j = 0; j < 2; j++)
            wmma::fill_fragment(acc[i][j], 0.0f);

    // prologue: stage 0 loads
    {
        cp_async16(&As[0][ar0][ac],      &X[(size_t)(bm + ar0)      * K + ac]);
        cp_async16(&As[0][ar0 + 64][ac], &X[(size_t)(bm + ar0 + 64) * K + ac]);
        cp_async16(&Bs[0][br][ac],       &Wt[(size_t)(bn + br)      * K + ac]);
        cp_commit();
    }

    int nk = K / GBK;
    int buf = 0;
    for (int ki = 0; ki < nk; ki++) {
        cp_wait0();
        __syncthreads();

        // prefetch next stage
        if (ki + 1 < nk) {
            int k0 = (ki + 1) * GBK;
            int nb2 = buf ^ 1;
            cp_async16(&As[nb2][ar0][ac],      &X[(size_t)(bm + ar0)      * K + k0 + ac]);
            cp_async16(&As[nb2][ar0 + 64][ac], &X[(size_t)(bm + ar0 + 64) * K + k0 + ac]);
            cp_async16(&Bs[nb2][br][ac],       &Wt[(size_t)(bn + br)      * K + k0 + ac]);
            cp_commit();
        } else {
            cp_commit();   // keep wait_group<0> semantics uniform
        }

#pragma unroll
        for (int kk = 0; kk < GBK; kk += 8) {
            wmma::fragment<wmma::matrix_a, 16, 16, 8, wmma::precision::tf32, wmma::row_major> af[2];
            wmma::fragment<wmma::matrix_b, 16, 16, 8, wmma::precision::tf32, wmma::col_major> bf[2];
#pragma unroll
            for (int mt = 0; mt < 2; mt++) {
                wmma::load_matrix_sync(af[mt], &As[buf][wm * 32 + mt * 16][kk], KPAD);
#pragma unroll
                for (int e = 0; e < af[mt].num_elements; e++)
                    af[mt].x[e] = wmma::__float_to_tf32(af[mt].x[e]);
            }
#pragma unroll
            for (int nt = 0; nt < 2; nt++) {
                wmma::load_matrix_sync(bf[nt], &Bs[buf][wn * 32 + nt * 16][kk], KPAD);
#pragma unroll
                for (int e = 0; e < bf[nt].num_elements; e++)
                    bf[nt].x[e] = wmma::__float_to_tf32(bf[nt].x[e]);
            }
#pragma unroll
            for (int mt = 0; mt < 2; mt++)
#pragma unroll
                for (int nt = 0; nt < 2; nt++)
                    wmma::mma_sync(acc[mt][nt], af[mt], bf[nt], acc[mt][nt]);
        }
        buf ^= 1;
    }

    cp_wait0();
    __syncthreads();
#pragma unroll
    for (int mt = 0; mt < 2; mt++)
#pragma unroll
        for (int nt = 0; nt < 2; nt++)
            wmma::store_matrix_sync(&Cs[wm * 32 + mt * 16][wn * 32 + nt * 16],
                                    acc[mt][nt], CPAD, wmma::mem_row_major);
    __syncthreads();

    for (int e = tid; e < GBM * GBN; e += 256) {
        int r = e >> 6, c = e & 63;
        float v = Cs[r][c] + bias[bn + c];
        size_t row = (size_t)(bm + r);
        int col = bn + c;
        if (EPI == 0) {
            dst[row * Ntot + col] = v;
        } else if (EPI == 1) {
            dst[row * Ntot + col] = gelu_exact(v);
        } else if (EPI == 2) {
            size_t g = (size_t)map[row];
            dst[g * CC + col] = res[g * CC + col] + v;
        } else {
            dst[row * CC + col] = res[row * CC + col] + v;
        }
    }
}

// ---------------- K3: fused window attention --------------------------------
// one CTA per (window, head); bias & shift-mask computed analytically
__global__ void __launch_bounds__(128)
attn_kernel(const float* __restrict__ qkv,
            const float* __restrict__ bias_table,
            float* __restrict__ out)
{
    int bw   = blockIdx.x;
    int head = blockIdx.y;
    int tid  = threadIdx.x;

    __shared__ float qs[NN][HD];
    __shared__ float ks[NN][HD];
    __shared__ float vs[NN][HD];
    __shared__ float sc[NN][52];
    __shared__ int   regid[NN];

    if (tid < NN) {
        int wi = bw & 63;
        int wh = wi >> 3, wwp = wi & 7;
        int r = tid / WSZ, s = tid - r * WSZ;
        int hh = wh * WSZ + r;
        int ww2 = wwp * WSZ + s;
        int rh = (hh < HH - WSZ) ? 0 : ((hh < HH - SSH) ? 1 : 2);
        int rw = (ww2 < WW - WSZ) ? 0 : ((ww2 < WW - SSH) ? 1 : 2);
        regid[tid] = rh * 3 + rw;
    }

    const float* base = qkv + (size_t)bw * NN * (3 * CC) + head * HD;
    for (int idx = tid; idx < NN * HD; idx += 128) {
        int n = idx >> 5, d = idx & 31;
        const float* p = base + (size_t)n * (3 * CC) + d;
        qs[n][d] = p[0];
        ks[n][d] = p[CC];
        vs[n][d] = p[2 * CC];
    }
    __syncthreads();

    const float scale = 0.17677669529663687f;   // 32^-0.5
    for (int idx = tid; idx < NN * NN; idx += 128) {
        int i = idx / NN, j = idx - i * NN;
        float d = 0.f;
#pragma unroll
        for (int t = 0; t < HD; t++) d += qs[i][t] * ks[j][t];
        int ih = i / WSZ, iw = i - ih * WSZ;
        int jh = j / WSZ, jw = j - jh * WSZ;
        int rel = (ih - jh + WSZ - 1) * (2 * WSZ - 1) + (iw - jw + WSZ - 1);
        float bv = bias_table[rel * NHD + head];
        float mv = (regid[i] != regid[j]) ? -100.0f : 0.0f;
        sc[i][j] = d * scale + bv + mv;
    }
    __syncthreads();

    int warp = tid >> 5, lane = tid & 31;
    for (int i = warp; i < NN; i += 4) {
        float v0 = sc[i][lane];
        float v1 = (lane + 32 < NN) ? sc[i][lane + 32] : -1e30f;
        float m = fmaxf(v0, v1);
#pragma unroll
        for (int o = 16; o; o >>= 1) m = fmaxf(m, __shfl_xor_sync(0xffffffffu, m, o));
        float e0 = __expf(v0 - m);
        float e1 = (lane + 32 < NN) ? __expf(v1 - m) : 0.f;
        float ssum = e0 + e1;
#pragma unroll
        for (int o = 16; o; o >>= 1) ssum += __shfl_xor_sync(0xffffffffu, ssum, o);
        float inv = 1.0f / ssum;
        sc[i][lane] = e0 * inv;
        if (lane + 32 < NN) sc[i][lane + 32] = e1 * inv;
    }
    __syncthreads();

    for (int idx = tid; idx < NN * HD; idx += 128) {
        int i = idx >> 5, d = idx & 31;
        float acc = 0.f;
#pragma unroll
        for (int j = 0; j < NN; j++) acc += sc[i][j] * vs[j][d];
        out[((size_t)bw * NN + i) * CC + head * HD + d] = acc;
    }
}

// ---------------- launch ----------------------------------------------------
extern "C" void kernel_launch(void* const* d_in, const int* in_sizes, int n_in,
                              void* d_out, int out_size)
{
    (void)in_sizes; (void)n_in; (void)out_size;
    const float* x        = (const float*)d_in[0];
    const float* norm_w   = (const float*)d_in[1];
    const float* norm_b   = (const float*)d_in[2];
    const float* qkv_w    = (const float*)d_in[3];
    const float* qkv_b    = (const float*)d_in[4];
    const float* rel_bias = (const float*)d_in[5];
    const float* proj_w   = (const float*)d_in[6];
    const float* proj_b   = (const float*)d_in[7];
    const float* fc1_w    = (const float*)d_in[8];
    const float* fc1_b    = (const float*)d_in[9];
    const float* fc2_w    = (const float*)d_in[10];
    const float* fc2_b    = (const float*)d_in[11];
    float* out = (float*)d_out;

    float *buf1, *buf2, *x1;
    int* map;
    cudaGetSymbolAddress((void**)&buf1, g_buf1);
    cudaGetSymbolAddress((void**)&buf2, g_buf2);
    cudaGetSymbolAddress((void**)&x1,   g_x1);
    cudaGetSymbolAddress((void**)&map,  g_map);

    // alias plan (stream-serialized, disjoint live ranges):
    float* xw  = buf1;   // live: steps 1-2
    float* att = buf1;   // live: steps 3-4
    float* h2  = buf1;   // live: steps 5-6
    float* qkv = buf2;   // live: steps 2-3 (MTOK*576 floats)
    float* hid = buf2;   // live: steps 6-7 (MTOK*768 floats)

    const int LN_BLOCKS = MTOK / 8;          // 12544
    const int GM = MTOK / GBM;               // 784

    // 1) LN + shift + window partition
    ln_shift_part_kernel<<<LN_BLOCKS, 256>>>(x, norm_w, norm_b, xw, map);
    // 2) qkv GEMM  (M x 576, K=192)
    gemm_tf32<0><<<dim3(GM, (3 * CC) / GBN), 256>>>(xw, qkv_w, qkv_b, qkv,
                                                    CC, 3 * CC, nullptr, nullptr);
    // 3) window attention
    attn_kernel<<<dim3(BW, NHD), 128>>>(qkv, rel_bias, att);
    // 4) proj GEMM + window-reverse/unshift scatter + residual
    gemm_tf32<2><<<dim3(GM, CC / GBN), 256>>>(att, proj_w, proj_b, x1,
                                              CC, CC, x, map);
    // 5) LN(x1)
    ln_plain_kernel<<<LN_BLOCKS, 256>>>(x1, norm_w, norm_b, h2);
    // 6) fc1 GEMM + exact GELU  (M x 768, K=192)
    gemm_tf32<1><<<dim3(GM, HID / GBN), 256>>>(h2, fc1_w, fc1_b, hid,
                                               CC, HID, nullptr, nullptr);
    // 7) fc2 GEMM + residual -> output  (M x 192, K=768)
    gemm_tf32<3><<<dim3(GM, CC / GBN), 256>>>(hid, fc2_w, fc2_b, out,
                                              HID, CC, x1, nullptr);
}

// round 7
// speedup vs baseline: 1.0018x; 1.0018x over previous
#include <cuda_runtime.h>
#include <cuda_bf16.h>
#include <mma.h>
#include <cstdint>

using namespace nvcuda;

// ---------------- problem constants ----------------
#define BB   32
#define HH   56
#define WW   56
#define CC   192
#define NHD  6
#define WSZ  7
#define SSH  3
#define NN   49          // WSZ*WSZ
#define HD   32          // CC/NHD
#define HID  768         // 4*CC
#define NWIN 64          // (H/WS)*(W/WS)
#define BW   2048        // BB*NWIN
#define MTOK 100352      // BW*NN  (= BB*HH*WW)

// ---------------- scratch (static device globals; aliased live ranges) ------
// g_buf1: xw (step1-2) -> att (step3-4) -> h2 (step5-6)
// g_buf2: qkv (step2-3, MTOK*576 floats) -> hid (step6-7, MTOK*768)
// g_x1  : live step4..end
__device__ float g_buf1[(size_t)MTOK * CC];
__device__ float g_buf2[(size_t)MTOK * HID];
__device__ float g_x1 [(size_t)MTOK * CC];
__device__ int   g_map[MTOK];

// ---------------- helpers ----------------------------------------------------
__device__ __forceinline__ uint32_t smem_u32(const void* p) {
    return (uint32_t)__cvta_generic_to_shared(p);
}
__device__ __forceinline__ void cp_async16(void* dst_smem, const void* src_g) {
    asm volatile("cp.async.cg.shared.global [%0], [%1], 16;\n"
                 :: "r"(smem_u32(dst_smem)), "l"(src_g));
}
__device__ __forceinline__ void cp_commit() {
    asm volatile("cp.async.commit_group;\n");
}
__device__ __forceinline__ void cp_wait0() {
    asm volatile("cp.async.wait_group 0;\n");
}

// ---------------- K1: LN + shift(-3,-3) + window partition ------------------
__global__ void __launch_bounds__(256)
ln_shift_part_kernel(const float* __restrict__ x,
                     const float* __restrict__ nw,
                     const float* __restrict__ nb,
                     float* __restrict__ xw,
                     int* __restrict__ map)
{
    int t    = blockIdx.x * 8 + (threadIdx.x >> 5);
    int lane = threadIdx.x & 31;

    int bw = t / NN, n = t - bw * NN;
    int b  = bw >> 6, wi = bw & 63;
    int wh = wi >> 3, wwp = wi & 7;
    int r  = n / WSZ, s = n - r * WSZ;
    int gh = wh * WSZ + r + SSH;  if (gh >= HH) gh -= HH;
    int gw = wwp * WSZ + s + SSH; if (gw >= WW) gw -= WW;
    int src = b * (HH * WW) + gh * WW + gw;

    const float* px = x + (size_t)src * CC;
    float v[6];
    float sum = 0.f, sq = 0.f;
#pragma unroll
    for (int i = 0; i < 6; i++) {
        v[i] = px[lane + i * 32];
        sum += v[i];
        sq  += v[i] * v[i];
    }
#pragma unroll
    for (int o = 16; o; o >>= 1) {
        sum += __shfl_xor_sync(0xffffffffu, sum, o);
        sq  += __shfl_xor_sync(0xffffffffu, sq,  o);
    }
    float mu   = sum * (1.f / CC);
    float var  = sq * (1.f / CC) - mu * mu;
    float rstd = rsqrtf(var + 1e-5f);

    float* po = xw + (size_t)t * CC;
#pragma unroll
    for (int i = 0; i < 6; i++) {
        int c = lane + i * 32;
        po[c] = (v[i] - mu) * rstd * nw[c] + nb[c];
    }
    if (lane == 0) map[t] = src;
}

// ---------------- K5: plain LN over x1 --------------------------------------
__global__ void __launch_bounds__(256)
ln_plain_kernel(const float* __restrict__ x,
                const float* __restrict__ nw,
                const float* __restrict__ nb,
                float* __restrict__ y)
{
    int t    = blockIdx.x * 8 + (threadIdx.x >> 5);
    int lane = threadIdx.x & 31;
    const float* px = x + (size_t)t * CC;
    float v[6];
    float sum = 0.f, sq = 0.f;
#pragma unroll
    for (int i = 0; i < 6; i++) {
        v[i] = px[lane + i * 32];
        sum += v[i];
        sq  += v[i] * v[i];
    }
#pragma unroll
    for (int o = 16; o; o >>= 1) {
        sum += __shfl_xor_sync(0xffffffffu, sum, o);
        sq  += __shfl_xor_sync(0xffffffffu, sq,  o);
    }
    float mu   = sum * (1.f / CC);
    float var  = sq * (1.f / CC) - mu * mu;
    float rstd = rsqrtf(var + 1e-5f);
    float* po = y + (size_t)t * CC;
#pragma unroll
    for (int i = 0; i < 6; i++) {
        int c = lane + i * 32;
        po[c] = (v[i] - mu) * rstd * nw[c] + nb[c];
    }
}

// ---------------- TF32 wmma GEMM:  Y[M,N] = X[M,K] @ W[N,K]^T + bias --------
// block tile 128x64, 8 warps (4x2), cp.async double-buffered mainloop.
#define GBM 128
#define GBN 64
#define GBK 16
#define KPAD 20          // floats per smem row (80 B, 16B-aligned)
#define CPAD 68

#define AS_FLOATS (2 * GBM * KPAD)           // 5120
#define BS_FLOATS (2 * GBN * KPAD)           // 2560
#define SMEM_FLOATS (GBM * CPAD)             // 8704 (>= 7680 pipeline floats)

__device__ __forceinline__ float gelu_exact(float v) {
    return 0.5f * v * (1.0f + erff(v * 0.70710678118654752f));
}

// EPI: 0=bias, 1=bias+gelu, 2=proj scatter (+x residual via map), 3=fc2 (+x1 residual)
template<int EPI>
__global__ void __launch_bounds__(256)
gemm_tf32(const float* __restrict__ X,
          const float* __restrict__ Wt,
          const float* __restrict__ bias,
          float* __restrict__ dst,
          int K, int Ntot,
          const float* __restrict__ res,
          const int* __restrict__ map)
{
    __shared__ __align__(16) float smem[SMEM_FLOATS];   // 34816 B, unioned
    float (*As)[GBM][KPAD] = (float(*)[GBM][KPAD])smem;             // As[2][GBM][KPAD]
    float (*Bs)[GBN][KPAD] = (float(*)[GBN][KPAD])(smem + AS_FLOATS); // Bs[2][GBN][KPAD]
    float (*Cs)[CPAD]      = (float(*)[CPAD])smem;

    int tid  = threadIdx.x;
    int warp = tid >> 5;
    int wm = warp & 3;       // 0..3  (M sub-tile)
    int wn = warp >> 2;      // 0..1  (N sub-tile)
    int bm = blockIdx.x * GBM;
    int bn = blockIdx.y * GBN;

    // per-thread load coordinates
    int ar0 = tid >> 2;               // A row for first float4 (0..63)
    int ac  = (tid & 3) << 2;         // A col (0,4,8,12)
    int br  = tid >> 2;               // B row (0..63)

    wmma::fragment<wmma::accumulator, 16, 16, 8, float> acc[2][2];
#pragma unroll
    for (int i = 0; i < 2; i++)
#pragma unroll
        for (int j = 0; j < 2; j++)
            wmma::fill_fragment(acc[i][j], 0.0f);

    // prologue: stage 0 loads
    {
        cp_async16(&As[0][ar0][ac],      &X[(size_t)(bm + ar0)      * K + ac]);
        cp_async16(&As[0][ar0 + 64][ac], &X[(size_t)(bm + ar0 + 64) * K + ac]);
        cp_async16(&Bs[0][br][ac],       &Wt[(size_t)(bn + br)      * K + ac]);
        cp_commit();
    }

    int nk = K / GBK;
    int buf = 0;
    for (int ki = 0; ki < nk; ki++) {
        cp_wait0();
        __syncthreads();

        // prefetch next stage
        if (ki + 1 < nk) {
            int k0 = (ki + 1) * GBK;
            int nb2 = buf ^ 1;
            cp_async16(&As[nb2][ar0][ac],      &X[(size_t)(bm + ar0)      * K + k0 + ac]);
            cp_async16(&As[nb2][ar0 + 64][ac], &X[(size_t)(bm + ar0 + 64) * K + k0 + ac]);
            cp_async16(&Bs[nb2][br][ac],       &Wt[(size_t)(bn + br)      * K + k0 + ac]);
            cp_commit();
        } else {
            cp_commit();   // keep wait_group<0> semantics uniform
        }

#pragma unroll
        for (int kk = 0; kk < GBK; kk += 8) {
            wmma::fragment<wmma::matrix_a, 16, 16, 8, wmma::precision::tf32, wmma::row_major> af[2];
            wmma::fragment<wmma::matrix_b, 16, 16, 8, wmma::precision::tf32, wmma::col_major> bf[2];
#pragma unroll
            for (int mt = 0; mt < 2; mt++) {
                wmma::load_matrix_sync(af[mt], &As[buf][wm * 32 + mt * 16][kk], KPAD);
#pragma unroll
                for (int e = 0; e < af[mt].num_elements; e++)
                    af[mt].x[e] = wmma::__float_to_tf32(af[mt].x[e]);
            }
#pragma unroll
            for (int nt = 0; nt < 2; nt++) {
                wmma::load_matrix_sync(bf[nt], &Bs[buf][wn * 32 + nt * 16][kk], KPAD);
#pragma unroll
                for (int e = 0; e < bf[nt].num_elements; e++)
                    bf[nt].x[e] = wmma::__float_to_tf32(bf[nt].x[e]);
            }
#pragma unroll
            for (int mt = 0; mt < 2; mt++)
#pragma unroll
                for (int nt = 0; nt < 2; nt++)
                    wmma::mma_sync(acc[mt][nt], af[mt], bf[nt], acc[mt][nt]);
        }
        buf ^= 1;
    }

    cp_wait0();
    __syncthreads();
#pragma unroll
    for (int mt = 0; mt < 2; mt++)
#pragma unroll
        for (int nt = 0; nt < 2; nt++)
            wmma::store_matrix_sync(&Cs[wm * 32 + mt * 16][wn * 32 + nt * 16],
                                    acc[mt][nt], CPAD, wmma::mem_row_major);
    __syncthreads();

    for (int e = tid; e < GBM * GBN; e += 256) {
        int r = e >> 6, c = e & 63;
        float v = Cs[r][c] + bias[bn + c];
        size_t row = (size_t)(bm + r);
        int col = bn + c;
        if (EPI == 0) {
            dst[row * Ntot + col] = v;
        } else if (EPI == 1) {
            dst[row * Ntot + col] = gelu_exact(v);
        } else if (EPI == 2) {
            size_t g = (size_t)map[row];
            dst[g * CC + col] = res[g * CC + col] + v;
        } else {
            dst[row * CC + col] = res[row * CC + col] + v;
        }
    }
}

// ---------------- K3: fused window attention --------------------------------
// one CTA per (window, head); bias & shift-mask computed analytically
__global__ void __launch_bounds__(128)
attn_kernel(const float* __restrict__ qkv,
            const float* __restrict__ bias_table,
            float* __restrict__ out)
{
    int bw   = blockIdx.x;
    int head = blockIdx.y;
    int tid  = threadIdx.x;

    __shared__ float qs[NN][HD];
    __shared__ float ks[NN][HD];
    __shared__ float vs[NN][HD];
    __shared__ float sc[NN][52];
    __shared__ int   regid[NN];

    if (tid < NN) {
        int wi = bw & 63;
        int wh = wi >> 3, wwp = wi & 7;
        int r = tid / WSZ, s = tid - r * WSZ;
        int hh = wh * WSZ + r;
        int ww2 = wwp * WSZ + s;
        int rh = (hh < HH - WSZ) ? 0 : ((hh < HH - SSH) ? 1 : 2);
        int rw = (ww2 < WW - WSZ) ? 0 : ((ww2 < WW - SSH) ? 1 : 2);
        regid[tid] = rh * 3 + rw;
    }

    const float* base = qkv + (size_t)bw * NN * (3 * CC) + head * HD;
    for (int idx = tid; idx < NN * HD; idx += 128) {
        int n = idx >> 5, d = idx & 31;
        const float* p = base + (size_t)n * (3 * CC) + d;
        qs[n][d] = p[0];
        ks[n][d] = p[CC];
        vs[n][d] = p[2 * CC];
    }
    __syncthreads();

    const float scale = 0.17677669529663687f;   // 32^-0.5
    for (int idx = tid; idx < NN * NN; idx += 128) {
        int i = idx / NN, j = idx - i * NN;
        float d = 0.f;
#pragma unroll
        for (int t = 0; t < HD; t++) d += qs[i][t] * ks[j][t];
        int ih = i / WSZ, iw = i - ih * WSZ;
        int jh = j / WSZ, jw = j - jh * WSZ;
        int rel = (ih - jh + WSZ - 1) * (2 * WSZ - 1) + (iw - jw + WSZ - 1);
        float bv = bias_table[rel * NHD + head];
        float mv = (regid[i] != regid[j]) ? -100.0f : 0.0f;
        sc[i][j] = d * scale + bv + mv;
    }
    __syncthreads();

    int warp = tid >> 5, lane = tid & 31;
    for (int i = warp; i < NN; i += 4) {
        float v0 = sc[i][lane];
        float v1 = (lane + 32 < NN) ? sc[i][lane + 32] : -1e30f;
        float m = fmaxf(v0, v1);
#pragma unroll
        for (int o = 16; o; o >>= 1) m = fmaxf(m, __shfl_xor_sync(0xffffffffu, m, o));
        float e0 = __expf(v0 - m);
        float e1 = (lane + 32 < NN) ? __expf(v1 - m) : 0.f;
        float ssum = e0 + e1;
#pragma unroll
        for (int o = 16; o; o >>= 1) ssum += __shfl_xor_sync(0xffffffffu, ssum, o);
        float inv = 1.0f / ssum;
        sc[i][lane] = e0 * inv;
        if (lane + 32 < NN) sc[i][lane + 32] = e1 * inv;
    }
    __syncthreads();

    for (int idx = tid; idx < NN * HD; idx += 128) {
        int i = idx >> 5, d = idx & 31;
        float acc = 0.f;
#pragma unroll
        for (int j = 0; j < NN; j++) acc += sc[i][j] * vs[j][d];
        out[((size_t)bw * NN + i) * CC + head * HD + d] = acc;
    }
}

// ---------------- launch ----------------------------------------------------
extern "C" void kernel_launch(void* const* d_in, const int* in_sizes, int n_in,
                              void* d_out, int out_size)
{
    (void)in_sizes; (void)n_in; (void)out_size;
    const float* x        = (const float*)d_in[0];
    const float* norm_w   = (const float*)d_in[1];
    const float* norm_b   = (const float*)d_in[2];
    const float* qkv_w    = (const float*)d_in[3];
    const float* qkv_b    = (const float*)d_in[4];
    const float* rel_bias = (const float*)d_in[5];
    const float* proj_w   = (const float*)d_in[6];
    const float* proj_b   = (const float*)d_in[7];
    const float* fc1_w    = (const float*)d_in[8];
    const float* fc1_b    = (const float*)d_in[9];
    const float* fc2_w    = (const float*)d_in[10];
    const float* fc2_b    = (const float*)d_in[11];
    float* out = (float*)d_out;

    float *buf1, *buf2, *x1;
    int* map;
    cudaGetSymbolAddress((void**)&buf1, g_buf1);
    cudaGetSymbolAddress((void**)&buf2, g_buf2);
    cudaGetSymbolAddress((void**)&x1,   g_x1);
    cudaGetSymbolAddress((void**)&map,  g_map);

    // alias plan (stream-serialized, disjoint live ranges):
    float* xw  = buf1;   // live: steps 1-2
    float* att = buf1;   // live: steps 3-4
    float* h2  = buf1;   // live: steps 5-6
    float* qkv = buf2;   // live: steps 2-3 (MTOK*576 floats)
    float* hid = buf2;   // live: steps 6-7 (MTOK*768 floats)

    const int LN_BLOCKS = MTOK / 8;          // 12544
    const int GM = MTOK / GBM;               // 784

    // 1) LN + shift + window partition
    ln_shift_part_kernel<<<LN_BLOCKS, 256>>>(x, norm_w, norm_b, xw, map);
    // 2) qkv GEMM  (M x 576, K=192)
    gemm_tf32<0><<<dim3(GM, (3 * CC) / GBN), 256>>>(xw, qkv_w, qkv_b, qkv,
                                                    CC, 3 * CC, nullptr, nullptr);
    // 3) window attention
    attn_kernel<<<dim3(BW, NHD), 128>>>(qkv, rel_bias, att);
    // 4) proj GEMM + window-reverse/unshift scatter + residual
    gemm_tf32<2><<<dim3(GM, CC / GBN), 256>>>(att, proj_w, proj_b, x1,
                                              CC, CC, x, map);
    // 5) LN(x1)
    ln_plain_kernel<<<LN_BLOCKS, 256>>>(x1, norm_w, norm_b, h2);
    // 6) fc1 GEMM + exact GELU  (M x 768, K=192)
    gemm_tf32<1><<<dim3(GM, HID / GBN), 256>>>(h2, fc1_w, fc1_b, hid,
                                               CC, HID, nullptr, nullptr);
    // 7) fc2 GEMM + residual -> output  (M x 192, K=768)
    gemm_tf32<3><<<dim3(GM, CC / GBN), 256>>>(hid, fc2_w, fc2_b, out,
                                              HID, CC, x1, nullptr);
}

// round 8
// speedup vs baseline: 1.0735x; 1.0716x over previous
#include <cuda_runtime.h>
#include <cuda_bf16.h>
#include <mma.h>
#include <cstdint>

using namespace nvcuda;

// ---------------- problem constants ----------------
#define BB   32
#define HH   56
#define WW   56
#define CC   192
#define NHD  6
#define WSZ  7
#define SSH  3
#define NN   49          // WSZ*WSZ
#define HD   32          // CC/NHD
#define HID  768         // 4*CC
#define NWIN 64          // (H/WS)*(W/WS)
#define BW   2048        // BB*NWIN
#define MTOK 100352      // BW*NN  (= BB*HH*WW)

// ---------------- scratch (static device globals; aliased live ranges) ------
__device__ float g_buf1[(size_t)MTOK * CC];
__device__ float g_buf2[(size_t)MTOK * HID];
__device__ float g_x1 [(size_t)MTOK * CC];
__device__ int   g_map[MTOK];

// ---------------- helpers ----------------------------------------------------
__device__ __forceinline__ uint32_t smem_u32(const void* p) {
    return (uint32_t)__cvta_generic_to_shared(p);
}
__device__ __forceinline__ void cp_async16(void* dst_smem, const void* src_g) {
    asm volatile("cp.async.cg.shared.global [%0], [%1], 16;\n"
                 :: "r"(smem_u32(dst_smem)), "l"(src_g));
}
__device__ __forceinline__ void cp_commit() {
    asm volatile("cp.async.commit_group;\n");
}
__device__ __forceinline__ void cp_wait0() {
    asm volatile("cp.async.wait_group 0;\n");
}

// ---------------- K1: LN + shift(-3,-3) + window partition ------------------
__global__ void __launch_bounds__(256)
ln_shift_part_kernel(const float* __restrict__ x,
                     const float* __restrict__ nw,
                     const float* __restrict__ nb,
                     float* __restrict__ xw,
                     int* __restrict__ map)
{
    int t    = blockIdx.x * 8 + (threadIdx.x >> 5);
    int lane = threadIdx.x & 31;

    int bw = t / NN, n = t - bw * NN;
    int b  = bw >> 6, wi = bw & 63;
    int wh = wi >> 3, wwp = wi & 7;
    int r  = n / WSZ, s = n - r * WSZ;
    int gh = wh * WSZ + r + SSH;  if (gh >= HH) gh -= HH;
    int gw = wwp * WSZ + s + SSH; if (gw >= WW) gw -= WW;
    int src = b * (HH * WW) + gh * WW + gw;

    const float* px = x + (size_t)src * CC;
    float v[6];
    float sum = 0.f, sq = 0.f;
#pragma unroll
    for (int i = 0; i < 6; i++) {
        v[i] = px[lane + i * 32];
        sum += v[i];
        sq  += v[i] * v[i];
    }
#pragma unroll
    for (int o = 16; o; o >>= 1) {
        sum += __shfl_xor_sync(0xffffffffu, sum, o);
        sq  += __shfl_xor_sync(0xffffffffu, sq,  o);
    }
    float mu   = sum * (1.f / CC);
    float var  = sq * (1.f / CC) - mu * mu;
    float rstd = rsqrtf(var + 1e-5f);

    float* po = xw + (size_t)t * CC;
#pragma unroll
    for (int i = 0; i < 6; i++) {
        int c = lane + i * 32;
        po[c] = (v[i] - mu) * rstd * nw[c] + nb[c];
    }
    if (lane == 0) map[t] = src;
}

// ---------------- K5: plain LN over x1 --------------------------------------
__global__ void __launch_bounds__(256)
ln_plain_kernel(const float* __restrict__ x,
                const float* __restrict__ nw,
                const float* __restrict__ nb,
                float* __restrict__ y)
{
    int t    = blockIdx.x * 8 + (threadIdx.x >> 5);
    int lane = threadIdx.x & 31;
    const float* px = x + (size_t)t * CC;
    float v[6];
    float sum = 0.f, sq = 0.f;
#pragma unroll
    for (int i = 0; i < 6; i++) {
        v[i] = px[lane + i * 32];
        sum += v[i];
        sq  += v[i] * v[i];
    }
#pragma unroll
    for (int o = 16; o; o >>= 1) {
        sum += __shfl_xor_sync(0xffffffffu, sum, o);
        sq  += __shfl_xor_sync(0xffffffffu, sq,  o);
    }
    float mu   = sum * (1.f / CC);
    float var  = sq * (1.f / CC) - mu * mu;
    float rstd = rsqrtf(var + 1e-5f);
    float* po = y + (size_t)t * CC;
#pragma unroll
    for (int i = 0; i < 6; i++) {
        int c = lane + i * 32;
        po[c] = (v[i] - mu) * rstd * nw[c] + nb[c];
    }
}

// ---------------- TF32 wmma GEMM:  Y[M,N] = X[M,K] @ W[N,K]^T + bias --------
// CTA tile 128x64, 4 warps (2M x 2N), warp tile 64x32 (4x2 frags),
// cp.async double-buffered mainloop, float4 epilogue.
#define GBM 128
#define GBN 64
#define GBK 16
#define KPAD 20          // floats per smem row (80 B, 16B-aligned)
#define CPAD 68

#define AS_FLOATS (2 * GBM * KPAD)           // 5120
#define BS_FLOATS (2 * GBN * KPAD)           // 2560
#define SMEM_FLOATS (GBM * CPAD)             // 8704 (>= 7680 pipeline floats)

__device__ __forceinline__ float gelu_exact(float v) {
    return 0.5f * v * (1.0f + erff(v * 0.70710678118654752f));
}

// EPI: 0=bias, 1=bias+gelu, 2=proj scatter (+x residual via map), 3=fc2 (+x1 residual)
template<int EPI>
__global__ void __launch_bounds__(128, 4)
gemm_tf32(const float* __restrict__ X,
          const float* __restrict__ Wt,
          const float* __restrict__ bias,
          float* __restrict__ dst,
          int K, int Ntot,
          const float* __restrict__ res,
          const int* __restrict__ map)
{
    __shared__ __align__(16) float smem[SMEM_FLOATS];   // 34816 B, unioned
    float (*As)[GBM][KPAD] = (float(*)[GBM][KPAD])smem;               // As[2][GBM][KPAD]
    float (*Bs)[GBN][KPAD] = (float(*)[GBN][KPAD])(smem + AS_FLOATS); // Bs[2][GBN][KPAD]
    float (*Cs)[CPAD]      = (float(*)[CPAD])smem;

    int tid  = threadIdx.x;          // 0..127
    int warp = tid >> 5;             // 0..3
    int wm = warp & 1;               // M half (64 rows)
    int wn = warp >> 1;              // N half (32 cols)
    int bm = blockIdx.x * GBM;
    int bn = blockIdx.y * GBN;

    // per-thread load coordinates (float4 granularity)
    int lr = tid >> 2;               // 0..31
    int lc = (tid & 3) << 2;         // 0,4,8,12

    wmma::fragment<wmma::accumulator, 16, 16, 8, float> acc[4][2];
#pragma unroll
    for (int i = 0; i < 4; i++)
#pragma unroll
        for (int j = 0; j < 2; j++)
            wmma::fill_fragment(acc[i][j], 0.0f);

    // prologue: stage 0 loads
    {
#pragma unroll
        for (int i = 0; i < 4; i++)
            cp_async16(&As[0][lr + i * 32][lc], &X[(size_t)(bm + lr + i * 32) * K + lc]);
#pragma unroll
        for (int i = 0; i < 2; i++)
            cp_async16(&Bs[0][lr + i * 32][lc], &Wt[(size_t)(bn + lr + i * 32) * K + lc]);
        cp_commit();
    }

    int nk = K / GBK;
    int buf = 0;
    for (int ki = 0; ki < nk; ki++) {
        cp_wait0();
        __syncthreads();

        // prefetch next stage
        if (ki + 1 < nk) {
            int k0 = (ki + 1) * GBK;
            int nb2 = buf ^ 1;
#pragma unroll
            for (int i = 0; i < 4; i++)
                cp_async16(&As[nb2][lr + i * 32][lc], &X[(size_t)(bm + lr + i * 32) * K + k0 + lc]);
#pragma unroll
            for (int i = 0; i < 2; i++)
                cp_async16(&Bs[nb2][lr + i * 32][lc], &Wt[(size_t)(bn + lr + i * 32) * K + k0 + lc]);
            cp_commit();
        } else {
            cp_commit();   // keep wait_group<0> semantics uniform
        }

#pragma unroll
        for (int kk = 0; kk < GBK; kk += 8) {
            wmma::fragment<wmma::matrix_a, 16, 16, 8, wmma::precision::tf32, wmma::row_major> af[4];
            wmma::fragment<wmma::matrix_b, 16, 16, 8, wmma::precision::tf32, wmma::col_major> bf[2];
#pragma unroll
            for (int mt = 0; mt < 4; mt++) {
                wmma::load_matrix_sync(af[mt], &As[buf][wm * 64 + mt * 16][kk], KPAD);
#pragma unroll
                for (int e = 0; e < af[mt].num_elements; e++)
                    af[mt].x[e] = wmma::__float_to_tf32(af[mt].x[e]);
            }
#pragma unroll
            for (int nt = 0; nt < 2; nt++) {
                wmma::load_matrix_sync(bf[nt], &Bs[buf][wn * 32 + nt * 16][kk], KPAD);
#pragma unroll
                for (int e = 0; e < bf[nt].num_elements; e++)
                    bf[nt].x[e] = wmma::__float_to_tf32(bf[nt].x[e]);
            }
#pragma unroll
            for (int mt = 0; mt < 4; mt++)
#pragma unroll
                for (int nt = 0; nt < 2; nt++)
                    wmma::mma_sync(acc[mt][nt], af[mt], bf[nt], acc[mt][nt]);
        }
        buf ^= 1;
    }

    cp_wait0();
    __syncthreads();
#pragma unroll
    for (int mt = 0; mt < 4; mt++)
#pragma unroll
        for (int nt = 0; nt < 2; nt++)
            wmma::store_matrix_sync(&Cs[wm * 64 + mt * 16][wn * 32 + nt * 16],
                                    acc[mt][nt], CPAD, wmma::mem_row_major);
    __syncthreads();

    // float4 epilogue: 128x64 elements = 2048 float4, 16 per thread
    for (int e = tid; e < (GBM * GBN) / 4; e += 128) {
        int r  = e >> 4;              // row 0..127
        int c4 = (e & 15) << 2;       // col 0,4,...,60
        float4 v = *(const float4*)&Cs[r][c4];
        float4 bb = *(const float4*)&bias[bn + c4];
        v.x += bb.x; v.y += bb.y; v.z += bb.z; v.w += bb.w;
        size_t row = (size_t)(bm + r);
        int col = bn + c4;
        if (EPI == 0) {
            *(float4*)&dst[row * Ntot + col] = v;
        } else if (EPI == 1) {
            v.x = gelu_exact(v.x); v.y = gelu_exact(v.y);
            v.z = gelu_exact(v.z); v.w = gelu_exact(v.w);
            *(float4*)&dst[row * Ntot + col] = v;
        } else if (EPI == 2) {
            size_t g = (size_t)map[row];
            float4 rr = *(const float4*)&res[g * CC + col];
            v.x += rr.x; v.y += rr.y; v.z += rr.z; v.w += rr.w;
            *(float4*)&dst[g * CC + col] = v;
        } else {
            float4 rr = *(const float4*)&res[row * CC + col];
            v.x += rr.x; v.y += rr.y; v.z += rr.z; v.w += rr.w;
            *(float4*)&dst[row * CC + col] = v;
        }
    }
}

// ---------------- K3: fused window attention --------------------------------
__global__ void __launch_bounds__(128)
attn_kernel(const float* __restrict__ qkv,
            const float* __restrict__ bias_table,
            float* __restrict__ out)
{
    int bw   = blockIdx.x;
    int head = blockIdx.y;
    int tid  = threadIdx.x;

    __shared__ float qs[NN][HD];
    __shared__ float ks[NN][HD];
    __shared__ float vs[NN][HD];
    __shared__ float sc[NN][52];
    __shared__ int   regid[NN];

    if (tid < NN) {
        int wi = bw & 63;
        int wh = wi >> 3, wwp = wi & 7;
        int r = tid / WSZ, s = tid - r * WSZ;
        int hh = wh * WSZ + r;
        int ww2 = wwp * WSZ + s;
        int rh = (hh < HH - WSZ) ? 0 : ((hh < HH - SSH) ? 1 : 2);
        int rw = (ww2 < WW - WSZ) ? 0 : ((ww2 < WW - SSH) ? 1 : 2);
        regid[tid] = rh * 3 + rw;
    }

    const float* base = qkv + (size_t)bw * NN * (3 * CC) + head * HD;
    for (int idx = tid; idx < NN * HD; idx += 128) {
        int n = idx >> 5, d = idx & 31;
        const float* p = base + (size_t)n * (3 * CC) + d;
        qs[n][d] = p[0];
        ks[n][d] = p[CC];
        vs[n][d] = p[2 * CC];
    }
    __syncthreads();

    const float scale = 0.17677669529663687f;   // 32^-0.5
    for (int idx = tid; idx < NN * NN; idx += 128) {
        int i = idx / NN, j = idx - i * NN;
        float d = 0.f;
#pragma unroll
        for (int t = 0; t < HD; t++) d += qs[i][t] * ks[j][t];
        int ih = i / WSZ, iw = i - ih * WSZ;
        int jh = j / WSZ, jw = j - jh * WSZ;
        int rel = (ih - jh + WSZ - 1) * (2 * WSZ - 1) + (iw - jw + WSZ - 1);
        float bv = bias_table[rel * NHD + head];
        float mv = (regid[i] != regid[j]) ? -100.0f : 0.0f;
        sc[i][j] = d * scale + bv + mv;
    }
    __syncthreads();

    int warp = tid >> 5, lane = tid & 31;
    for (int i = warp; i < NN; i += 4) {
        float v0 = sc[i][lane];
        float v1 = (lane + 32 < NN) ? sc[i][lane + 32] : -1e30f;
        float m = fmaxf(v0, v1);
#pragma unroll
        for (int o = 16; o; o >>= 1) m = fmaxf(m, __shfl_xor_sync(0xffffffffu, m, o));
        float e0 = __expf(v0 - m);
        float e1 = (lane + 32 < NN) ? __expf(v1 - m) : 0.f;
        float ssum = e0 + e1;
#pragma unroll
        for (int o = 16; o; o >>= 1) ssum += __shfl_xor_sync(0xffffffffu, ssum, o);
        float inv = 1.0f / ssum;
        sc[i][lane] = e0 * inv;
        if (lane + 32 < NN) sc[i][lane + 32] = e1 * inv;
    }
    __syncthreads();

    for (int idx = tid; idx < NN * HD; idx += 128) {
        int i = idx >> 5, d = idx & 31;
        float acc = 0.f;
#pragma unroll
        for (int j = 0; j < NN; j++) acc += sc[i][j] * vs[j][d];
        out[((size_t)bw * NN + i) * CC + head * HD + d] = acc;
    }
}

// ---------------- launch ----------------------------------------------------
extern "C" void kernel_launch(void* const* d_in, const int* in_sizes, int n_in,
                              void* d_out, int out_size)
{
    (void)in_sizes; (void)n_in; (void)out_size;
    const float* x        = (const float*)d_in[0];
    const float* norm_w   = (const float*)d_in[1];
    const float* norm_b   = (const float*)d_in[2];
    const float* qkv_w    = (const float*)d_in[3];
    const float* qkv_b    = (const float*)d_in[4];
    const float* rel_bias = (const float*)d_in[5];
    const float* proj_w   = (const float*)d_in[6];
    const float* proj_b   = (const float*)d_in[7];
    const float* fc1_w    = (const float*)d_in[8];
    const float* fc1_b    = (const float*)d_in[9];
    const float* fc2_w    = (const float*)d_in[10];
    const float* fc2_b    = (const float*)d_in[11];
    float* out = (float*)d_out;

    float *buf1, *buf2, *x1;
    int* map;
    cudaGetSymbolAddress((void**)&buf1, g_buf1);
    cudaGetSymbolAddress((void**)&buf2, g_buf2);
    cudaGetSymbolAddress((void**)&x1,   g_x1);
    cudaGetSymbolAddress((void**)&map,  g_map);

    // alias plan (stream-serialized, disjoint live ranges):
    float* xw  = buf1;   // live: steps 1-2
    float* att = buf1;   // live: steps 3-4
    float* h2  = buf1;   // live: steps 5-6
    float* qkv = buf2;   // live: steps 2-3 (MTOK*576 floats)
    float* hid = buf2;   // live: steps 6-7 (MTOK*768 floats)

    const int LN_BLOCKS = MTOK / 8;          // 12544
    const int GM = MTOK / GBM;               // 784

    // 1) LN + shift + window partition
    ln_shift_part_kernel<<<LN_BLOCKS, 256>>>(x, norm_w, norm_b, xw, map);
    // 2) qkv GEMM  (M x 576, K=192)
    gemm_tf32<0><<<dim3(GM, (3 * CC) / GBN), 128>>>(xw, qkv_w, qkv_b, qkv,
                                                    CC, 3 * CC, nullptr, nullptr);
    // 3) window attention
    attn_kernel<<<dim3(BW, NHD), 128>>>(qkv, rel_bias, att);
    // 4) proj GEMM + window-reverse/unshift scatter + residual
    gemm_tf32<2><<<dim3(GM, CC / GBN), 128>>>(att, proj_w, proj_b, x1,
                                              CC, CC, x, map);
    // 5) LN(x1)
    ln_plain_kernel<<<LN_BLOCKS, 256>>>(x1, norm_w, norm_b, h2);
    // 6) fc1 GEMM + exact GELU  (M x 768, K=192)
    gemm_tf32<1><<<dim3(GM, HID / GBN), 128>>>(h2, fc1_w, fc1_b, hid,
                                               CC, HID, nullptr, nullptr);
    // 7) fc2 GEMM + residual -> output  (M x 192, K=768)
    gemm_tf32<3><<<dim3(GM, CC / GBN), 128>>>(hid, fc2_w, fc2_b, out,
                                              HID, CC, x1, nullptr);
}

// round 9
// speedup vs baseline: 1.1109x; 1.0348x over previous
#include <cuda_runtime.h>
#include <cuda_bf16.h>
#include <mma.h>
#include <cstdint>

using namespace nvcuda;

// ---------------- problem constants ----------------
#define BB   32
#define HH   56
#define WW   56
#define CC   192
#define NHD  6
#define WSZ  7
#define SSH  3
#define NN   49          // WSZ*WSZ
#define HD   32          // CC/NHD
#define HID  768         // 4*CC
#define NWIN 64          // (H/WS)*(W/WS)
#define BW   2048        // BB*NWIN
#define MTOK 100352      // BW*NN  (= BB*HH*WW)

// weight scratch offsets (floats)
#define WOFF_QKV 0
#define WOFF_PROJ 110592              // 576*192
#define WOFF_FC1 147456               // + 192*192
#define WOFF_FC2 294912               // + 768*192
#define WTOTAL   442368               // + 192*768

// ---------------- scratch (static device globals; aliased live ranges) ------
__device__ float g_buf1[(size_t)MTOK * CC];
__device__ float g_buf2[(size_t)MTOK * HID];
__device__ float g_x1 [(size_t)MTOK * CC];
__device__ float g_wbuf[WTOTAL];
__device__ int   g_map[MTOK];

// ---------------- helpers ----------------------------------------------------
__device__ __forceinline__ uint32_t smem_u32(const void* p) {
    return (uint32_t)__cvta_generic_to_shared(p);
}
__device__ __forceinline__ void cp_async16(void* dst_smem, const void* src_g) {
    asm volatile("cp.async.cg.shared.global [%0], [%1], 16;\n"
                 :: "r"(smem_u32(dst_smem)), "l"(src_g));
}
__device__ __forceinline__ void cp_commit() {
    asm volatile("cp.async.commit_group;\n");
}
__device__ __forceinline__ void cp_wait0() {
    asm volatile("cp.async.wait_group 0;\n");
}
__device__ __forceinline__ void cp_wait1() {
    asm volatile("cp.async.wait_group 1;\n");
}
__device__ __forceinline__ float rtf32(float x) {   // round-to-nearest tf32
    return wmma::__float_to_tf32(x);
}

// ---------------- K0: pre-round weights to tf32 ------------------------------
__global__ void __launch_bounds__(256)
round_weights_kernel(const float* __restrict__ qkvw,
                     const float* __restrict__ projw,
                     const float* __restrict__ fc1w,
                     const float* __restrict__ fc2w,
                     float* __restrict__ wb)
{
    int i = blockIdx.x * 256 + threadIdx.x;
    if (i < WOFF_PROJ)       wb[i] = rtf32(qkvw[i - WOFF_QKV]);
    else if (i < WOFF_FC1)   wb[i] = rtf32(projw[i - WOFF_PROJ]);
    else if (i < WOFF_FC2)   wb[i] = rtf32(fc1w[i - WOFF_FC1]);
    else if (i < WTOTAL)     wb[i] = rtf32(fc2w[i - WOFF_FC2]);
}

// ---------------- K1: LN + shift(-3,-3) + window partition ------------------
// ROUND=1: output rounded to tf32 (feeds a GEMM A operand)
template<int ROUND>
__global__ void __launch_bounds__(256)
ln_shift_part_kernel(const float* __restrict__ x,
                     const float* __restrict__ nw,
                     const float* __restrict__ nb,
                     float* __restrict__ xw,
                     int* __restrict__ map)
{
    int t    = blockIdx.x * 8 + (threadIdx.x >> 5);
    int lane = threadIdx.x & 31;

    int bw = t / NN, n = t - bw * NN;
    int b  = bw >> 6, wi = bw & 63;
    int wh = wi >> 3, wwp = wi & 7;
    int r  = n / WSZ, s = n - r * WSZ;
    int gh = wh * WSZ + r + SSH;  if (gh >= HH) gh -= HH;
    int gw = wwp * WSZ + s + SSH; if (gw >= WW) gw -= WW;
    int src = b * (HH * WW) + gh * WW + gw;

    const float* px = x + (size_t)src * CC;
    float v[6];
    float sum = 0.f, sq = 0.f;
#pragma unroll
    for (int i = 0; i < 6; i++) {
        v[i] = px[lane + i * 32];
        sum += v[i];
        sq  += v[i] * v[i];
    }
#pragma unroll
    for (int o = 16; o; o >>= 1) {
        sum += __shfl_xor_sync(0xffffffffu, sum, o);
        sq  += __shfl_xor_sync(0xffffffffu, sq,  o);
    }
    float mu   = sum * (1.f / CC);
    float var  = sq * (1.f / CC) - mu * mu;
    float rstd = rsqrtf(var + 1e-5f);

    float* po = xw + (size_t)t * CC;
#pragma unroll
    for (int i = 0; i < 6; i++) {
        int c = lane + i * 32;
        float y = (v[i] - mu) * rstd * nw[c] + nb[c];
        po[c] = ROUND ? rtf32(y) : y;
    }
    if (lane == 0) map[t] = src;
}

// ---------------- K5: plain LN over x1 (rounded: feeds fc1) ------------------
__global__ void __launch_bounds__(256)
ln_plain_kernel(const float* __restrict__ x,
                const float* __restrict__ nw,
                const float* __restrict__ nb,
                float* __restrict__ y)
{
    int t    = blockIdx.x * 8 + (threadIdx.x >> 5);
    int lane = threadIdx.x & 31;
    const float* px = x + (size_t)t * CC;
    float v[6];
    float sum = 0.f, sq = 0.f;
#pragma unroll
    for (int i = 0; i < 6; i++) {
        v[i] = px[lane + i * 32];
        sum += v[i];
        sq  += v[i] * v[i];
    }
#pragma unroll
    for (int o = 16; o; o >>= 1) {
        sum += __shfl_xor_sync(0xffffffffu, sum, o);
        sq  += __shfl_xor_sync(0xffffffffu, sq,  o);
    }
    float mu   = sum * (1.f / CC);
    float var  = sq * (1.f / CC) - mu * mu;
    float rstd = rsqrtf(var + 1e-5f);
    float* po = y + (size_t)t * CC;
#pragma unroll
    for (int i = 0; i < 6; i++) {
        int c = lane + i * 32;
        po[c] = rtf32((v[i] - mu) * rstd * nw[c] + nb[c]);
    }
}

// ---------------- TF32 wmma GEMM:  Y[M,N] = X[M,K] @ W[N,K]^T + bias --------
// CTA tile 128x64, 4 warps (2M x 2N), warp tile 64x32 (4x2 frags),
// 3-stage cp.async pipeline (wait_group 1), inputs pre-rounded to tf32.
#define GBM 128
#define GBN 64
#define GBK 16
#define KPAD 20          // floats per smem row (80 B, 16B-aligned)
#define CPAD 68
#define NSTG 3

#define STG_FLOATS ((GBM + GBN) * KPAD)        // 3840
#define SMEM_FLOATS (NSTG * STG_FLOATS)        // 11520 (46080 B); epilogue 8704 unions

__device__ __forceinline__ float gelu_exact(float v) {
    return 0.5f * v * (1.0f + erff(v * 0.70710678118654752f));
}

// EPI: 0=bias, 1=bias+gelu (rounded), 2=proj scatter (+x residual), 3=fc2 (+x1 residual)
template<int EPI>
__global__ void __launch_bounds__(128, 4)
gemm_tf32(const float* __restrict__ X,
          const float* __restrict__ Wt,
          const float* __restrict__ bias,
          float* __restrict__ dst,
          int K, int Ntot,
          const float* __restrict__ res,
          const int* __restrict__ map)
{
    __shared__ __align__(16) float smem[SMEM_FLOATS];
    float (*As)[GBM][KPAD] = (float(*)[GBM][KPAD])smem;   // As[s] at s*STG_FLOATS
    float (*Cs)[CPAD]      = (float(*)[CPAD])smem;

    int tid  = threadIdx.x;          // 0..127
    int warp = tid >> 5;             // 0..3
    int wm = warp & 1;               // M half (64 rows)
    int wn = warp >> 1;              // N half (32 cols)
    int bm = blockIdx.x * GBM;
    int bn = blockIdx.y * GBN;

    // per-thread load coordinates (float4 granularity)
    int lr = tid >> 2;               // 0..31
    int lc = (tid & 3) << 2;         // 0,4,8,12

    wmma::fragment<wmma::accumulator, 16, 16, 8, float> acc[4][2];
#pragma unroll
    for (int i = 0; i < 4; i++)
#pragma unroll
        for (int j = 0; j < 2; j++)
            wmma::fill_fragment(acc[i][j], 0.0f);

    // stage smem helpers
    auto a_ptr = [&](int s, int r, int c) -> float* {
        return &smem[s * STG_FLOATS + r * KPAD + c];
    };
    auto b_ptr = [&](int s, int r, int c) -> float* {
        return &smem[s * STG_FLOATS + GBM * KPAD + r * KPAD + c];
    };

    auto issue_stage = [&](int s, int k0) {
#pragma unroll
        for (int i = 0; i < 4; i++)
            cp_async16(a_ptr(s, lr + i * 32, lc), &X[(size_t)(bm + lr + i * 32) * K + k0 + lc]);
#pragma unroll
        for (int i = 0; i < 2; i++)
            cp_async16(b_ptr(s, lr + i * 32, lc), &Wt[(size_t)(bn + lr + i * 32) * K + k0 + lc]);
        cp_commit();
    };

    int nk = K / GBK;                // >= 12
    // prologue: stage 0, 1
    issue_stage(0, 0);
    issue_stage(1, GBK);

    int s = 0;
    for (int ki = 0; ki < nk; ki++) {
        cp_wait1();                  // stage ki resident
        __syncthreads();

        if (ki + 2 < nk)
            issue_stage((s + 2) % NSTG, (ki + 2) * GBK);

#pragma unroll
        for (int kk = 0; kk < GBK; kk += 8) {
            wmma::fragment<wmma::matrix_a, 16, 16, 8, wmma::precision::tf32, wmma::row_major> af[4];
            wmma::fragment<wmma::matrix_b, 16, 16, 8, wmma::precision::tf32, wmma::col_major> bf[2];
#pragma unroll
            for (int mt = 0; mt < 4; mt++)
                wmma::load_matrix_sync(af[mt], a_ptr(s, wm * 64 + mt * 16, kk), KPAD);
#pragma unroll
            for (int nt = 0; nt < 2; nt++)
                wmma::load_matrix_sync(bf[nt], b_ptr(s, wn * 32 + nt * 16, kk), KPAD);
#pragma unroll
            for (int mt = 0; mt < 4; mt++)
#pragma unroll
                for (int nt = 0; nt < 2; nt++)
                    wmma::mma_sync(acc[mt][nt], af[mt], bf[nt], acc[mt][nt]);
        }
        s = (s + 1) % NSTG;
        __syncthreads();             // compute done before buffer s reused 2 iters later
    }

    cp_wait0();
    __syncthreads();
#pragma unroll
    for (int mt = 0; mt < 4; mt++)
#pragma unroll
        for (int nt = 0; nt < 2; nt++)
            wmma::store_matrix_sync(&Cs[wm * 64 + mt * 16][wn * 32 + nt * 16],
                                    acc[mt][nt], CPAD, wmma::mem_row_major);
    __syncthreads();

    // float4 epilogue: 128x64 elements = 2048 float4, 16 per thread
    for (int e = tid; e < (GBM * GBN) / 4; e += 128) {
        int r  = e >> 4;              // row 0..127
        int c4 = (e & 15) << 2;       // col 0,4,...,60
        float4 v = *(const float4*)&Cs[r][c4];
        float4 bb = *(const float4*)&bias[bn + c4];
        v.x += bb.x; v.y += bb.y; v.z += bb.z; v.w += bb.w;
        size_t row = (size_t)(bm + r);
        int col = bn + c4;
        if (EPI == 0) {
            *(float4*)&dst[row * Ntot + col] = v;
        } else if (EPI == 1) {
            v.x = rtf32(gelu_exact(v.x)); v.y = rtf32(gelu_exact(v.y));
            v.z = rtf32(gelu_exact(v.z)); v.w = rtf32(gelu_exact(v.w));
            *(float4*)&dst[row * Ntot + col] = v;
        } else if (EPI == 2) {
            size_t g = (size_t)map[row];
            float4 rr = *(const float4*)&res[g * CC + col];
            v.x += rr.x; v.y += rr.y; v.z += rr.z; v.w += rr.w;
            *(float4*)&dst[g * CC + col] = v;
        } else {
            float4 rr = *(const float4*)&res[row * CC + col];
            v.x += rr.x; v.y += rr.y; v.z += rr.z; v.w += rr.w;
            *(float4*)&dst[row * CC + col] = v;
        }
    }
}

// ---------------- K3: fused window attention --------------------------------
// output rounded to tf32 (feeds proj GEMM A operand)
__global__ void __launch_bounds__(128)
attn_kernel(const float* __restrict__ qkv,
            const float* __restrict__ bias_table,
            float* __restrict__ out)
{
    int bw   = blockIdx.x;
    int head = blockIdx.y;
    int tid  = threadIdx.x;

    __shared__ float qs[NN][HD];
    __shared__ float ks[NN][HD];
    __shared__ float vs[NN][HD];
    __shared__ float sc[NN][52];
    __shared__ int   regid[NN];

    if (tid < NN) {
        int wi = bw & 63;
        int wh = wi >> 3, wwp = wi & 7;
        int r = tid / WSZ, s = tid - r * WSZ;
        int hh = wh * WSZ + r;
        int ww2 = wwp * WSZ + s;
        int rh = (hh < HH - WSZ) ? 0 : ((hh < HH - SSH) ? 1 : 2);
        int rw = (ww2 < WW - WSZ) ? 0 : ((ww2 < WW - SSH) ? 1 : 2);
        regid[tid] = rh * 3 + rw;
    }

    const float* base = qkv + (size_t)bw * NN * (3 * CC) + head * HD;
    for (int idx = tid; idx < NN * HD; idx += 128) {
        int n = idx >> 5, d = idx & 31;
        const float* p = base + (size_t)n * (3 * CC) + d;
        qs[n][d] = p[0];
        ks[n][d] = p[CC];
        vs[n][d] = p[2 * CC];
    }
    __syncthreads();

    const float scale = 0.17677669529663687f;   // 32^-0.5
    for (int idx = tid; idx < NN * NN; idx += 128) {
        int i = idx / NN, j = idx - i * NN;
        float d = 0.f;
#pragma unroll
        for (int t = 0; t < HD; t++) d += qs[i][t] * ks[j][t];
        int ih = i / WSZ, iw = i - ih * WSZ;
        int jh = j / WSZ, jw = j - jh * WSZ;
        int rel = (ih - jh + WSZ - 1) * (2 * WSZ - 1) + (iw - jw + WSZ - 1);
        float bv = bias_table[rel * NHD + head];
        float mv = (regid[i] != regid[j]) ? -100.0f : 0.0f;
        sc[i][j] = d * scale + bv + mv;
    }
    __syncthreads();

    int warp = tid >> 5, lane = tid & 31;
    for (int i = warp; i < NN; i += 4) {
        float v0 = sc[i][lane];
        float v1 = (lane + 32 < NN) ? sc[i][lane + 32] : -1e30f;
        float m = fmaxf(v0, v1);
#pragma unroll
        for (int o = 16; o; o >>= 1) m = fmaxf(m, __shfl_xor_sync(0xffffffffu, m, o));
        float e0 = __expf(v0 - m);
        float e1 = (lane + 32 < NN) ? __expf(v1 - m) : 0.f;
        float ssum = e0 + e1;
#pragma unroll
        for (int o = 16; o; o >>= 1) ssum += __shfl_xor_sync(0xffffffffu, ssum, o);
        float inv = 1.0f / ssum;
        sc[i][lane] = e0 * inv;
        if (lane + 32 < NN) sc[i][lane + 32] = e1 * inv;
    }
    __syncthreads();

    for (int idx = tid; idx < NN * HD; idx += 128) {
        int i = idx >> 5, d = idx & 31;
        float acc = 0.f;
#pragma unroll
        for (int j = 0; j < NN; j++) acc += sc[i][j] * vs[j][d];
        out[((size_t)bw * NN + i) * CC + head * HD + d] = rtf32(acc);
    }
}

// ---------------- launch ----------------------------------------------------
extern "C" void kernel_launch(void* const* d_in, const int* in_sizes, int n_in,
                              void* d_out, int out_size)
{
    (void)in_sizes; (void)n_in; (void)out_size;
    const float* x        = (const float*)d_in[0];
    const float* norm_w   = (const float*)d_in[1];
    const float* norm_b   = (const float*)d_in[2];
    const float* qkv_w    = (const float*)d_in[3];
    const float* qkv_b    = (const float*)d_in[4];
    const float* rel_bias = (const float*)d_in[5];
    const float* proj_w   = (const float*)d_in[6];
    const float* proj_b   = (const float*)d_in[7];
    const float* fc1_w    = (const float*)d_in[8];
    const float* fc1_b    = (const float*)d_in[9];
    const float* fc2_w    = (const float*)d_in[10];
    const float* fc2_b    = (const float*)d_in[11];
    float* out = (float*)d_out;

    float *buf1, *buf2, *x1, *wb;
    int* map;
    cudaGetSymbolAddress((void**)&buf1, g_buf1);
    cudaGetSymbolAddress((void**)&buf2, g_buf2);
    cudaGetSymbolAddress((void**)&x1,   g_x1);
    cudaGetSymbolAddress((void**)&wb,   g_wbuf);
    cudaGetSymbolAddress((void**)&map,  g_map);

    // alias plan (stream-serialized, disjoint live ranges):
    float* xw  = buf1;   // live: steps 1-2
    float* att = buf1;   // live: steps 3-4
    float* h2  = buf1;   // live: steps 5-6
    float* qkv = buf2;   // live: steps 2-3 (MTOK*576 floats)
    float* hid = buf2;   // live: steps 6-7 (MTOK*768 floats)

    const int LN_BLOCKS = MTOK / 8;          // 12544
    const int GM = MTOK / GBM;               // 784

    // 0) pre-round weights to tf32
    round_weights_kernel<<<(WTOTAL + 255) / 256, 256>>>(qkv_w, proj_w, fc1_w, fc2_w, wb);
    // 1) LN + shift + window partition (rounded output)
    ln_shift_part_kernel<1><<<LN_BLOCKS, 256>>>(x, norm_w, norm_b, xw, map);
    // 2) qkv GEMM  (M x 576, K=192)
    gemm_tf32<0><<<dim3(GM, (3 * CC) / GBN), 128>>>(xw, wb + WOFF_QKV, qkv_b, qkv,
                                                    CC, 3 * CC, nullptr, nullptr);
    // 3) window attention (rounded output)
    attn_kernel<<<dim3(BW, NHD), 128>>>(qkv, rel_bias, att);
    // 4) proj GEMM + window-reverse/unshift scatter + residual
    gemm_tf32<2><<<dim3(GM, CC / GBN), 128>>>(att, wb + WOFF_PROJ, proj_b, x1,
                                              CC, CC, x, map);
    // 5) LN(x1) (rounded output)
    ln_plain_kernel<<<LN_BLOCKS, 256>>>(x1, norm_w, norm_b, h2);
    // 6) fc1 GEMM + exact GELU (rounded output)
    gemm_tf32<1><<<dim3(GM, HID / GBN), 128>>>(h2, wb + WOFF_FC1, fc1_b, hid,
                                               CC, HID, nullptr, nullptr);
    // 7) fc2 GEMM + residual -> output
    gemm_tf32<3><<<dim3(GM, CC / GBN), 128>>>(hid, wb + WOFF_FC2, fc2_b, out,
                                              HID, CC, x1, nullptr);
}

// round 10
// speedup vs baseline: 1.1111x; 1.0002x over previous
#include <cuda_runtime.h>
#include <cuda_bf16.h>
#include <mma.h>
#include <cstdint>

using namespace nvcuda;

// ---------------- problem constants ----------------
#define BB   32
#define HH   56
#define WW   56
#define CC   192
#define NHD  6
#define WSZ  7
#define SSH  3
#define NN   49          // WSZ*WSZ
#define HD   32          // CC/NHD
#define HID  768         // 4*CC
#define NWIN 64          // (H/WS)*(W/WS)
#define BW   2048        // BB*NWIN
#define MTOK 100352      // BW*NN  (= BB*HH*WW)

// weight scratch offsets (floats)
#define WOFF_QKV 0
#define WOFF_PROJ 110592              // 576*192
#define WOFF_FC1 147456               // + 192*192
#define WOFF_FC2 294912               // + 768*192
#define WTOTAL   442368               // + 192*768

// ---------------- scratch (static device globals; aliased live ranges) ------
__device__ float g_buf1[(size_t)MTOK * CC];
__device__ float g_buf2[(size_t)MTOK * HID];
__device__ float g_x1 [(size_t)MTOK * CC];
__device__ float g_wbuf[WTOTAL];
__device__ int   g_map[MTOK];

// ---------------- helpers ----------------------------------------------------
__device__ __forceinline__ uint32_t smem_u32(const void* p) {
    return (uint32_t)__cvta_generic_to_shared(p);
}
__device__ __forceinline__ void cp_async16(void* dst_smem, const void* src_g) {
    asm volatile("cp.async.cg.shared.global [%0], [%1], 16;\n"
                 :: "r"(smem_u32(dst_smem)), "l"(src_g));
}
__device__ __forceinline__ void cp_commit() {
    asm volatile("cp.async.commit_group;\n");
}
__device__ __forceinline__ void cp_wait0() {
    asm volatile("cp.async.wait_group 0;\n");
}
__device__ __forceinline__ void cp_wait1() {
    asm volatile("cp.async.wait_group 1;\n");
}
__device__ __forceinline__ float rtf32(float x) {   // round-to-nearest tf32
    return wmma::__float_to_tf32(x);
}

// ---------------- K0: pre-round weights to tf32 ------------------------------
__global__ void __launch_bounds__(256)
round_weights_kernel(const float* __restrict__ qkvw,
                     const float* __restrict__ projw,
                     const float* __restrict__ fc1w,
                     const float* __restrict__ fc2w,
                     float* __restrict__ wb)
{
    int i = blockIdx.x * 256 + threadIdx.x;
    if (i < WOFF_PROJ)       wb[i] = rtf32(qkvw[i - WOFF_QKV]);
    else if (i < WOFF_FC1)   wb[i] = rtf32(projw[i - WOFF_PROJ]);
    else if (i < WOFF_FC2)   wb[i] = rtf32(fc1w[i - WOFF_FC1]);
    else if (i < WTOTAL)     wb[i] = rtf32(fc2w[i - WOFF_FC2]);
}

// ---------------- K1: LN + shift(-3,-3) + window partition ------------------
// ROUND=1: output rounded to tf32 (feeds a GEMM A operand)
template<int ROUND>
__global__ void __launch_bounds__(256)
ln_shift_part_kernel(const float* __restrict__ x,
                     const float* __restrict__ nw,
                     const float* __restrict__ nb,
                     float* __restrict__ xw,
                     int* __restrict__ map)
{
    int t    = blockIdx.x * 8 + (threadIdx.x >> 5);
    int lane = threadIdx.x & 31;

    int bw = t / NN, n = t - bw * NN;
    int b  = bw >> 6, wi = bw & 63;
    int wh = wi >> 3, wwp = wi & 7;
    int r  = n / WSZ, s = n - r * WSZ;
    int gh = wh * WSZ + r + SSH;  if (gh >= HH) gh -= HH;
    int gw = wwp * WSZ + s + SSH; if (gw >= WW) gw -= WW;
    int src = b * (HH * WW) + gh * WW + gw;

    const float* px = x + (size_t)src * CC;
    float v[6];
    float sum = 0.f, sq = 0.f;
#pragma unroll
    for (int i = 0; i < 6; i++) {
        v[i] = px[lane + i * 32];
        sum += v[i];
        sq  += v[i] * v[i];
    }
#pragma unroll
    for (int o = 16; o; o >>= 1) {
        sum += __shfl_xor_sync(0xffffffffu, sum, o);
        sq  += __shfl_xor_sync(0xffffffffu, sq,  o);
    }
    float mu   = sum * (1.f / CC);
    float var  = sq * (1.f / CC) - mu * mu;
    float rstd = rsqrtf(var + 1e-5f);

    float* po = xw + (size_t)t * CC;
#pragma unroll
    for (int i = 0; i < 6; i++) {
        int c = lane + i * 32;
        float y = (v[i] - mu) * rstd * nw[c] + nb[c];
        po[c] = ROUND ? rtf32(y) : y;
    }
    if (lane == 0) map[t] = src;
}

// ---------------- K5: plain LN over x1 (rounded: feeds fc1) ------------------
__global__ void __launch_bounds__(256)
ln_plain_kernel(const float* __restrict__ x,
                const float* __restrict__ nw,
                const float* __restrict__ nb,
                float* __restrict__ y)
{
    int t    = blockIdx.x * 8 + (threadIdx.x >> 5);
    int lane = threadIdx.x & 31;
    const float* px = x + (size_t)t * CC;
    float v[6];
    float sum = 0.f, sq = 0.f;
#pragma unroll
    for (int i = 0; i < 6; i++) {
        v[i] = px[lane + i * 32];
        sum += v[i];
        sq  += v[i] * v[i];
    }
#pragma unroll
    for (int o = 16; o; o >>= 1) {
        sum += __shfl_xor_sync(0xffffffffu, sum, o);
        sq  += __shfl_xor_sync(0xffffffffu, sq,  o);
    }
    float mu   = sum * (1.f / CC);
    float var  = sq * (1.f / CC) - mu * mu;
    float rstd = rsqrtf(var + 1e-5f);
    float* po = y + (size_t)t * CC;
#pragma unroll
    for (int i = 0; i < 6; i++) {
        int c = lane + i * 32;
        po[c] = rtf32((v[i] - mu) * rstd * nw[c] + nb[c]);
    }
}

// ---------------- TF32 wmma GEMM:  Y[M,N] = X[M,K] @ W[N,K]^T + bias --------
// CTA tile 128x64, 4 warps (2M x 2N), warp tile 64x32 (4x2 frags),
// 3-stage cp.async pipeline (wait_group 1), inputs pre-rounded to tf32.
#define GBM 128
#define GBN 64
#define GBK 16
#define KPAD 20          // floats per smem row (80 B, 16B-aligned)
#define CPAD 68
#define NSTG 3

#define STG_FLOATS ((GBM + GBN) * KPAD)        // 3840
#define SMEM_FLOATS (NSTG * STG_FLOATS)        // 11520 (46080 B); epilogue 8704 unions

__device__ __forceinline__ float gelu_exact(float v) {
    return 0.5f * v * (1.0f + erff(v * 0.70710678118654752f));
}

// EPI: 0=bias, 1=bias+gelu (rounded), 2=proj scatter (+x residual), 3=fc2 (+x1 residual)
template<int EPI>
__global__ void __launch_bounds__(128, 4)
gemm_tf32(const float* __restrict__ X,
          const float* __restrict__ Wt,
          const float* __restrict__ bias,
          float* __restrict__ dst,
          int K, int Ntot,
          const float* __restrict__ res,
          const int* __restrict__ map)
{
    __shared__ __align__(16) float smem[SMEM_FLOATS];
    float (*As)[GBM][KPAD] = (float(*)[GBM][KPAD])smem;   // As[s] at s*STG_FLOATS
    float (*Cs)[CPAD]      = (float(*)[CPAD])smem;

    int tid  = threadIdx.x;          // 0..127
    int warp = tid >> 5;             // 0..3
    int wm = warp & 1;               // M half (64 rows)
    int wn = warp >> 1;              // N half (32 cols)
    int bm = blockIdx.x * GBM;
    int bn = blockIdx.y * GBN;

    // per-thread load coordinates (float4 granularity)
    int lr = tid >> 2;               // 0..31
    int lc = (tid & 3) << 2;         // 0,4,8,12

    wmma::fragment<wmma::accumulator, 16, 16, 8, float> acc[4][2];
#pragma unroll
    for (int i = 0; i < 4; i++)
#pragma unroll
        for (int j = 0; j < 2; j++)
            wmma::fill_fragment(acc[i][j], 0.0f);

    // stage smem helpers
    auto a_ptr = [&](int s, int r, int c) -> float* {
        return &smem[s * STG_FLOATS + r * KPAD + c];
    };
    auto b_ptr = [&](int s, int r, int c) -> float* {
        return &smem[s * STG_FLOATS + GBM * KPAD + r * KPAD + c];
    };

    auto issue_stage = [&](int s, int k0) {
#pragma unroll
        for (int i = 0; i < 4; i++)
            cp_async16(a_ptr(s, lr + i * 32, lc), &X[(size_t)(bm + lr + i * 32) * K + k0 + lc]);
#pragma unroll
        for (int i = 0; i < 2; i++)
            cp_async16(b_ptr(s, lr + i * 32, lc), &Wt[(size_t)(bn + lr + i * 32) * K + k0 + lc]);
        cp_commit();
    };

    int nk = K / GBK;                // >= 12
    // prologue: stage 0, 1
    issue_stage(0, 0);
    issue_stage(1, GBK);

    int s = 0;
    for (int ki = 0; ki < nk; ki++) {
        cp_wait1();                  // stage ki resident
        __syncthreads();

        if (ki + 2 < nk)
            issue_stage((s + 2) % NSTG, (ki + 2) * GBK);

#pragma unroll
        for (int kk = 0; kk < GBK; kk += 8) {
            wmma::fragment<wmma::matrix_a, 16, 16, 8, wmma::precision::tf32, wmma::row_major> af[4];
            wmma::fragment<wmma::matrix_b, 16, 16, 8, wmma::precision::tf32, wmma::col_major> bf[2];
#pragma unroll
            for (int mt = 0; mt < 4; mt++)
                wmma::load_matrix_sync(af[mt], a_ptr(s, wm * 64 + mt * 16, kk), KPAD);
#pragma unroll
            for (int nt = 0; nt < 2; nt++)
                wmma::load_matrix_sync(bf[nt], b_ptr(s, wn * 32 + nt * 16, kk), KPAD);
#pragma unroll
            for (int mt = 0; mt < 4; mt++)
#pragma unroll
                for (int nt = 0; nt < 2; nt++)
                    wmma::mma_sync(acc[mt][nt], af[mt], bf[nt], acc[mt][nt]);
        }
        s = (s + 1) % NSTG;
        __syncthreads();             // compute done before buffer s reused 2 iters later
    }

    cp_wait0();
    __syncthreads();
#pragma unroll
    for (int mt = 0; mt < 4; mt++)
#pragma unroll
        for (int nt = 0; nt < 2; nt++)
            wmma::store_matrix_sync(&Cs[wm * 64 + mt * 16][wn * 32 + nt * 16],
                                    acc[mt][nt], CPAD, wmma::mem_row_major);
    __syncthreads();

    // float4 epilogue: 128x64 elements = 2048 float4, 16 per thread
    for (int e = tid; e < (GBM * GBN) / 4; e += 128) {
        int r  = e >> 4;              // row 0..127
        int c4 = (e & 15) << 2;       // col 0,4,...,60
        float4 v = *(const float4*)&Cs[r][c4];
        float4 bb = *(const float4*)&bias[bn + c4];
        v.x += bb.x; v.y += bb.y; v.z += bb.z; v.w += bb.w;
        size_t row = (size_t)(bm + r);
        int col = bn + c4;
        if (EPI == 0) {
            *(float4*)&dst[row * Ntot + col] = v;
        } else if (EPI == 1) {
            v.x = rtf32(gelu_exact(v.x)); v.y = rtf32(gelu_exact(v.y));
            v.z = rtf32(gelu_exact(v.z)); v.w = rtf32(gelu_exact(v.w));
            *(float4*)&dst[row * Ntot + col] = v;
        } else if (EPI == 2) {
            size_t g = (size_t)map[row];
            float4 rr = *(const float4*)&res[g * CC + col];
            v.x += rr.x; v.y += rr.y; v.z += rr.z; v.w += rr.w;
            *(float4*)&dst[g * CC + col] = v;
        } else {
            float4 rr = *(const float4*)&res[row * CC + col];
            v.x += rr.x; v.y += rr.y; v.z += rr.z; v.w += rr.w;
            *(float4*)&dst[row * CC + col] = v;
        }
    }
}

// ---------------- K3: fused window attention --------------------------------
// output rounded to tf32 (feeds proj GEMM A operand)
__global__ void __launch_bounds__(128)
attn_kernel(const float* __restrict__ qkv,
            const float* __restrict__ bias_table,
            float* __restrict__ out)
{
    int bw   = blockIdx.x;
    int head = blockIdx.y;
    int tid  = threadIdx.x;

    __shared__ float qs[NN][HD];
    __shared__ float ks[NN][HD];
    __shared__ float vs[NN][HD];
    __shared__ float sc[NN][52];
    __shared__ int   regid[NN];

    if (tid < NN) {
        int wi = bw & 63;
        int wh = wi >> 3, wwp = wi & 7;
        int r = tid / WSZ, s = tid - r * WSZ;
        int hh = wh * WSZ + r;
        int ww2 = wwp * WSZ + s;
        int rh = (hh < HH - WSZ) ? 0 : ((hh < HH - SSH) ? 1 : 2);
        int rw = (ww2 < WW - WSZ) ? 0 : ((ww2 < WW - SSH) ? 1 : 2);
        regid[tid] = rh * 3 + rw;
    }

    const float* base = qkv + (size_t)bw * NN * (3 * CC) + head * HD;
    for (int idx = tid; idx < NN * HD; idx += 128) {
        int n = idx >> 5, d = idx & 31;
        const float* p = base + (size_t)n * (3 * CC) + d;
        qs[n][d] = p[0];
        ks[n][d] = p[CC];
        vs[n][d] = p[2 * CC];
    }
    __syncthreads();

    const float scale = 0.17677669529663687f;   // 32^-0.5
    for (int idx = tid; idx < NN * NN; idx += 128) {
        int i = idx / NN, j = idx - i * NN;
        float d = 0.f;
#pragma unroll
        for (int t = 0; t < HD; t++) d += qs[i][t] * ks[j][t];
        int ih = i / WSZ, iw = i - ih * WSZ;
        int jh = j / WSZ, jw = j - jh * WSZ;
        int rel = (ih - jh + WSZ - 1) * (2 * WSZ - 1) + (iw - jw + WSZ - 1);
        float bv = bias_table[rel * NHD + head];
        float mv = (regid[i] != regid[j]) ? -100.0f : 0.0f;
        sc[i][j] = d * scale + bv + mv;
    }
    __syncthreads();

    int warp = tid >> 5, lane = tid & 31;
    for (int i = warp; i < NN; i += 4) {
        float v0 = sc[i][lane];
        float v1 = (lane + 32 < NN) ? sc[i][lane + 32] : -1e30f;
        float m = fmaxf(v0, v1);
#pragma unroll
        for (int o = 16; o; o >>= 1) m = fmaxf(m, __shfl_xor_sync(0xffffffffu, m, o));
        float e0 = __expf(v0 - m);
        float e1 = (lane + 32 < NN) ? __expf(v1 - m) : 0.f;
        float ssum = e0 + e1;
#pragma unroll
        for (int o = 16; o; o >>= 1) ssum += __shfl_xor_sync(0xffffffffu, ssum, o);
        float inv = 1.0f / ssum;
        sc[i][lane] = e0 * inv;
        if (lane + 32 < NN) sc[i][lane + 32] = e1 * inv;
    }
    __syncthreads();

    for (int idx = tid; idx < NN * HD; idx += 128) {
        int i = idx >> 5, d = idx & 31;
        float acc = 0.f;
#pragma unroll
        for (int j = 0; j < NN; j++) acc += sc[i][j] * vs[j][d];
        out[((size_t)bw * NN + i) * CC + head * HD + d] = rtf32(acc);
    }
}

// ---------------- launch ----------------------------------------------------
extern "C" void kernel_launch(void* const* d_in, const int* in_sizes, int n_in,
                              void* d_out, int out_size)
{
    (void)in_sizes; (void)n_in; (void)out_size;
    const float* x        = (const float*)d_in[0];
    const float* norm_w   = (const float*)d_in[1];
    const float* norm_b   = (const float*)d_in[2];
    const float* qkv_w    = (const float*)d_in[3];
    const float* qkv_b    = (const float*)d_in[4];
    const float* rel_bias = (const float*)d_in[5];
    const float* proj_w   = (const float*)d_in[6];
    const float* proj_b   = (const float*)d_in[7];
    const float* fc1_w    = (const float*)d_in[8];
    const float* fc1_b    = (const float*)d_in[9];
    const float* fc2_w    = (const float*)d_in[10];
    const float* fc2_b    = (const float*)d_in[11];
    float* out = (float*)d_out;

    float *buf1, *buf2, *x1, *wb;
    int* map;
    cudaGetSymbolAddress((void**)&buf1, g_buf1);
    cudaGetSymbolAddress((void**)&buf2, g_buf2);
    cudaGetSymbolAddress((void**)&x1,   g_x1);
    cudaGetSymbolAddress((void**)&wb,   g_wbuf);
    cudaGetSymbolAddress((void**)&map,  g_map);

    // alias plan (stream-serialized, disjoint live ranges):
    float* xw  = buf1;   // live: steps 1-2
    float* att = buf1;   // live: steps 3-4
    float* h2  = buf1;   // live: steps 5-6
    float* qkv = buf2;   // live: steps 2-3 (MTOK*576 floats)
    float* hid = buf2;   // live: steps 6-7 (MTOK*768 floats)

    const int LN_BLOCKS = MTOK / 8;          // 12544
    const int GM = MTOK / GBM;               // 784

    // 0) pre-round weights to tf32
    round_weights_kernel<<<(WTOTAL + 255) / 256, 256>>>(qkv_w, proj_w, fc1_w, fc2_w, wb);
    // 1) LN + shift + window partition (rounded output)
    ln_shift_part_kernel<1><<<LN_BLOCKS, 256>>>(x, norm_w, norm_b, xw, map);
    // 2) qkv GEMM  (M x 576, K=192)
    gemm_tf32<0><<<dim3(GM, (3 * CC) / GBN), 128>>>(xw, wb + WOFF_QKV, qkv_b, qkv,
                                                    CC, 3 * CC, nullptr, nullptr);
    // 3) window attention (rounded output)
    attn_kernel<<<dim3(BW, NHD), 128>>>(qkv, rel_bias, att);
    // 4) proj GEMM + window-reverse/unshift scatter + residual
    gemm_tf32<2><<<dim3(GM, CC / GBN), 128>>>(att, wb + WOFF_PROJ, proj_b, x1,
                                              CC, CC, x, map);
    // 5) LN(x1) (rounded output)
    ln_plain_kernel<<<LN_BLOCKS, 256>>>(x1, norm_w, norm_b, h2);
    // 6) fc1 GEMM + exact GELU (rounded output)
    gemm_tf32<1><<<dim3(GM, HID / GBN), 128>>>(h2, wb + WOFF_FC1, fc1_b, hid,
                                               CC, HID, nullptr, nullptr);
    // 7) fc2 GEMM + residual -> output
    gemm_tf32<3><<<dim3(GM, CC / GBN), 128>>>(hid, wb + WOFF_FC2, fc2_b, out,
                                              HID, CC, x1, nullptr);
}